// round 7
// baseline (speedup 1.0000x reference)
#include <cuda_runtime.h>
#include <cstdint>
#include <cstddef>

#define NROWS 4096
#define ODIM  512
#define IDIM  512
#define DDIM  64

#define BM 128
#define BN 64
#define NTH 256
#define NTILES 513            // 512 W tiles (i) + 1 bias tile

#define BPITCHF 72u                         // floats per B d-row (72 mod 32 = 8 -> conflict-free)
#define B_STAGE (64u * BPITCHF * 4u)        // 18432 B
#define VPITCHF 68u                         // floats per var row (68 mod 32 = 4 -> conflict-free)
#define V_OFF   (4u * B_STAGE)              // 73728
#define V_BYTES (128u * VPITCHF * 4u)       // 34816
#define SMEM_TOTAL (int)(V_OFF + V_BYTES)   // 108544 B  (<= 113KB -> 2 CTAs/SM)

__device__ float g_xT[IDIM * NROWS];   // x transposed: [512][4096]

// ---------------- helpers ----------------
__device__ __forceinline__ uint32_t smem_u32(const void* p) {
    uint32_t a;
    asm("{ .reg .u64 t; cvta.to.shared.u64 t, %1; cvt.u32.u64 %0, t; }" : "=r"(a) : "l"(p));
    return a;
}
__device__ __forceinline__ uint32_t f2tf32(float f) {
    uint32_t r;
    asm("cvt.rna.tf32.f32 %0, %1;" : "=r"(r) : "f"(f));
    return r;
}
#define CP_ASYNC16(dst, src) \
    asm volatile("cp.async.cg.shared.global [%0], [%1], 16;" :: "r"(dst), "l"(src) : "memory")
#define CP_COMMIT() asm volatile("cp.async.commit_group;" ::: "memory")
#define CP_WAIT2()  asm volatile("cp.async.wait_group 2;" ::: "memory")

#define LDS32(v, a)  asm volatile("ld.shared.b32 %0, [%1];" : "=r"(v) : "r"(a))
#define LDS32F(v, a) asm volatile("ld.shared.b32 %0, [%1];" : "=f"(v) : "r"(a))

__device__ __forceinline__ void mma_tf32_16x8x8(float& c0, float& c1, float& c2, float& c3,
                                                uint32_t a0, uint32_t a1, uint32_t a2, uint32_t a3,
                                                uint32_t b0, uint32_t b1) {
    asm volatile(
        "mma.sync.aligned.m16n8k8.row.col.f32.tf32.tf32.f32 "
        "{%0,%1,%2,%3}, {%4,%5,%6,%7}, {%8,%9}, {%0,%1,%2,%3};"
        : "+f"(c0), "+f"(c1), "+f"(c2), "+f"(c3)
        : "r"(a0), "r"(a1), "r"(a2), "r"(a3), "r"(b0), "r"(b1));
}

// ---------------- x transpose ----------------
__global__ void __launch_bounds__(1024) transpose_x(const float* __restrict__ x) {
    __shared__ float t[32][33];
    const int bi = blockIdx.x * 32;
    const int bn = blockIdx.y * 32;
    t[threadIdx.y][threadIdx.x] = x[(size_t)(bn + threadIdx.y) * IDIM + bi + threadIdx.x];
    __syncthreads();
    g_xT[(size_t)(bi + threadIdx.y) * NROWS + bn + threadIdx.x] = t[threadIdx.x][threadIdx.y];
}

// ---------------- main kernel: 2 CTAs/SM, var in SMEM ----------------
__global__ void __launch_bounds__(NTH, 2) mlp_mma(
    const float* __restrict__ var,
    const float* __restrict__ W,
    const float* __restrict__ b1,
    float* __restrict__ out)
{
    extern __shared__ __align__(128) uint8_t smem[];
    const uint32_t s0 = smem_u32(smem);
    const uint32_t vS = s0 + V_OFF;

    const int tid  = threadIdx.x;
    const int lane = tid & 31;
    const int w    = tid >> 5;
    const int rowBase = blockIdx.y * BM;
    const int colBase = blockIdx.x * BN;

    const int wm = (w & 3) * 32;    // warp m-base (4 warps over M)
    const int wn = (w >> 2) * 32;   // warp n-base (2 warps over N)
    const int c  = lane & 3;        // k-index within quad
    const int og = lane >> 2;       // row/col group

    // ----- stage var tile into SMEM: var_s[m][d], pitch 68 floats -----
    for (int idx = tid; idx < BM * DDIM; idx += NTH) {
        int m = idx >> 6, d = idx & 63;
        float vv = __ldg(&var[(size_t)(rowBase + m) * DDIM + d]);
        asm volatile("st.shared.b32 [%0], %1;" ::
            "r"(vS + ((uint32_t)m * VPITCHF + (uint32_t)d) * 4u), "f"(vv) : "memory");
    }

    // ----- this thread's 4 fragment rows -----
    int xr[4];
    uint32_t vAddr[4];
#pragma unroll
    for (int rr = 0; rr < 4; ++rr) {
        int mloc = wm + (rr >> 1) * 16 + (rr & 1) * 8 + og;
        xr[rr] = rowBase + mloc;
        vAddr[rr] = vS + ((uint32_t)mloc * VPITCHF + (uint32_t)c) * 4u;
    }

    // ----- B loader constants (cp.async) -----
    const int brow = tid >> 2;                 // d row 0..63
    const int bco  = (tid & 3) * 16;           // float offset (this thread's 64B chunk)
    const uint32_t bDst = s0 + ((uint32_t)brow * BPITCHF + (uint32_t)(tid & 3) * 16u) * 4u;
    const float* bW = W + (size_t)brow * IDIM * ODIM + colBase + bco;   // + t*ODIM
    const float* bB = b1 + (size_t)brow * ODIM + colBase + bco;

    auto issueB = [&](int t) {
        const float* src = (t < 512) ? (bW + (size_t)t * ODIM) : bB;
        const uint32_t d = bDst + (uint32_t)(t & 3) * B_STAGE;
#pragma unroll
        for (int c4 = 0; c4 < 4; ++c4)
            CP_ASYNC16(d + (uint32_t)c4 * 16u, src + c4 * 4);
        CP_COMMIT();
    };
    auto loadX = [&](int t, float* dst) {
        if (t < 512) {
#pragma unroll
            for (int rr = 0; rr < 4; ++rr)
                dst[rr] = __ldg(&g_xT[(size_t)t * NROWS + xr[rr]]);
        } else {
#pragma unroll
            for (int rr = 0; rr < 4; ++rr) dst[rr] = 1.0f;
        }
    };

    float C[2][4][4];
#pragma unroll
    for (int mt = 0; mt < 2; ++mt)
#pragma unroll
        for (int nt = 0; nt < 4; ++nt)
#pragma unroll
            for (int q = 0; q < 4; ++q) C[mt][nt][q] = 0.0f;

    // ----- prologue -----
    issueB(0); issueB(1); issueB(2);
    float xc[4], xn[4];
    loadX(0, xc);
    __syncthreads();   // var_s ready

    const uint32_t bColOff = (uint32_t)(wn + og) * 4u;

    // ----- mainloop: one __syncthreads per tile -----
    for (int i = 0; i < NTILES; ++i) {
        CP_WAIT2();
        __syncthreads();

        if (i + 3 <= 512) issueB(i + 3);
        loadX(i + 1, xn);

        const uint32_t bB0 = s0 + (uint32_t)(i & 3) * B_STAGE;

#pragma unroll
        for (int ks = 0; ks < 8; ++ks) {
            const uint32_t d0 = (uint32_t)(8 * ks) * 4u;        // byte offset of d = 8ks+c (c in vAddr)
            // B fragments
            const uint32_t rAddr = bB0 + ((uint32_t)(8 * ks + c) * BPITCHF) * 4u + bColOff;
            uint32_t b[4][2];
#pragma unroll
            for (int nt = 0; nt < 4; ++nt) {
                LDS32(b[nt][0], rAddr + (uint32_t)nt * 32u);
                LDS32(b[nt][1], rAddr + 4u * BPITCHF * 4u + (uint32_t)nt * 32u);
            }
            // A fragments: v from SMEM, x from registers
            uint32_t a[2][4];
#pragma unroll
            for (int mt = 0; mt < 2; ++mt) {
                float v00, v10, v01, v11;
                LDS32F(v00, vAddr[mt * 2 + 0] + d0);
                LDS32F(v10, vAddr[mt * 2 + 1] + d0);
                LDS32F(v01, vAddr[mt * 2 + 0] + d0 + 16u);
                LDS32F(v11, vAddr[mt * 2 + 1] + d0 + 16u);
                a[mt][0] = f2tf32(xc[mt * 2 + 0] * v00);
                a[mt][1] = f2tf32(xc[mt * 2 + 1] * v10);
                a[mt][2] = f2tf32(xc[mt * 2 + 0] * v01);
                a[mt][3] = f2tf32(xc[mt * 2 + 1] * v11);
            }
#pragma unroll
            for (int mt = 0; mt < 2; ++mt)
#pragma unroll
                for (int nt = 0; nt < 4; ++nt)
                    mma_tf32_16x8x8(C[mt][nt][0], C[mt][nt][1], C[mt][nt][2], C[mt][nt][3],
                                    a[mt][0], a[mt][1], a[mt][2], a[mt][3],
                                    b[nt][0], b[nt][1]);
        }

#pragma unroll
        for (int rr = 0; rr < 4; ++rr) xc[rr] = xn[rr];
    }

    // ----- epilogue: compensate tf32 RZ-truncation of B with (1 + 2^-11) -----
    const float SCL = 1.00048828125f;
#pragma unroll
    for (int mt = 0; mt < 2; ++mt) {
        const int r0 = rowBase + wm + mt * 16 + og;
#pragma unroll
        for (int nt = 0; nt < 4; ++nt) {
            const int c0 = colBase + wn + nt * 8 + c * 2;
            float2 v0, v1;
            v0.x = C[mt][nt][0] * SCL; v0.y = C[mt][nt][1] * SCL;
            v1.x = C[mt][nt][2] * SCL; v1.y = C[mt][nt][3] * SCL;
            *reinterpret_cast<float2*>(&out[(size_t)r0 * ODIM + c0]) = v0;
            *reinterpret_cast<float2*>(&out[(size_t)(r0 + 8) * ODIM + c0]) = v1;
        }
    }
}

// ---------------- host ----------------
extern "C" void kernel_launch(void* const* d_in, const int* in_sizes, int n_in,
                              void* d_out, int out_size) {
    const float* x   = (const float*)d_in[0];   // [4096, 512]
    const float* var = (const float*)d_in[1];   // [4096, 64]
    const float* W   = (const float*)d_in[2];   // [64, 512, 512]
    const float* b1  = (const float*)d_in[3];   // [64, 512]
    float* out       = (float*)d_out;           // [4096, 512]

    {
        dim3 tb(32, 32), tg(IDIM / 32, NROWS / 32);
        transpose_x<<<tg, tb>>>(x);
    }

    cudaFuncSetAttribute(mlp_mma, cudaFuncAttributeMaxDynamicSharedMemorySize, SMEM_TOTAL);
    dim3 grid(ODIM / BN, NROWS / BM);   // (8, 32) = 256 CTAs, 2 per SM
    mlp_mma<<<grid, NTH, SMEM_TOTAL>>>(var, W, b1, out);
}

// round 8
// speedup vs baseline: 2.4103x; 2.4103x over previous
#include <cuda_runtime.h>
#include <cuda_fp16.h>
#include <cstdint>
#include <cstddef>

#define NROWS 4096
#define ODIM  512
#define IDIM  512
#define DDIM  64

#define BM 128
#define BN 64
#define NTH 256
#define NT_W 256            // W tiles, each covering 2 consecutive i (BK = 128)
#define NTILES 257          // + bias half-tile

#define BPITCHB 272u                       // bytes per o-row in B stage (128 fp16 + 8 pad): 68 b32 ≡ 4 mod 32
#define B_STAGE (64u * BPITCHB)            // 17408 B
#define V_OFF   (4u * B_STAGE)             // 69632
#define VPITCHB 144u                       // bytes per m-row of vh (32 fp16x2 + pad): 36 b32 ≡ 4 mod 32
#define SMEM_TOTAL (int)(V_OFF + 128u * VPITCHB)   // 88064 B -> 2 CTAs/SM (227KB)

__device__ float  g_xT[IDIM * NROWS];                  // x transposed: [512][4096] fp32
__device__ __half g_Wt[(size_t)IDIM * ODIM * DDIM];    // W re-laid: [i][o][d] fp16
__device__ __half g_bt[ODIM * DDIM];                   // b1 re-laid: [o][d] fp16

// ---------------- helpers ----------------
__device__ __forceinline__ uint32_t smem_u32(const void* p) {
    uint32_t a;
    asm("{ .reg .u64 t; cvta.to.shared.u64 t, %1; cvt.u32.u64 %0, t; }" : "=r"(a) : "l"(p));
    return a;
}
__device__ __forceinline__ uint32_t f2h2(float f) {   // (h,h) packed fp16x2
    uint32_t r;
    asm("{ .reg .b16 h; cvt.rn.f16.f32 h, %1; mov.b32 %0, {h, h}; }" : "=r"(r) : "f"(f));
    return r;
}
#define CP_ASYNC16(dst, src) \
    asm volatile("cp.async.cg.shared.global [%0], [%1], 16;" :: "r"(dst), "l"(src) : "memory")
#define CP_COMMIT() asm volatile("cp.async.commit_group;" ::: "memory")
#define CP_WAIT2()  asm volatile("cp.async.wait_group 2;" ::: "memory")

#define LDS32(v, a) asm volatile("ld.shared.b32 %0, [%1];" : "=r"(v) : "r"(a))
#define HMUL2(d, a, b) asm("mul.rn.f16x2 %0, %1, %2;" : "=r"(d) : "r"(a), "r"(b))

__device__ __forceinline__ void mma_f16_16816(float& c0, float& c1, float& c2, float& c3,
                                              uint32_t a0, uint32_t a1, uint32_t a2, uint32_t a3,
                                              uint32_t b0, uint32_t b1) {
    asm volatile(
        "mma.sync.aligned.m16n8k16.row.col.f32.f16.f16.f32 "
        "{%0,%1,%2,%3}, {%4,%5,%6,%7}, {%8,%9}, {%0,%1,%2,%3};"
        : "+f"(c0), "+f"(c1), "+f"(c2), "+f"(c3)
        : "r"(a0), "r"(a1), "r"(a2), "r"(a3), "r"(b0), "r"(b1));
}

// ---------------- prepass kernels ----------------
__global__ void __launch_bounds__(1024) transpose_x(const float* __restrict__ x) {
    __shared__ float t[32][33];
    const int bi = blockIdx.x * 32;
    const int bn = blockIdx.y * 32;
    t[threadIdx.y][threadIdx.x] = x[(size_t)(bn + threadIdx.y) * IDIM + bi + threadIdx.x];
    __syncthreads();
    g_xT[(size_t)(bi + threadIdx.y) * NROWS + bn + threadIdx.x] = t[threadIdx.x][threadIdx.y];
}

// W[d][i][o] fp32 -> g_Wt[i][o][d] fp16
__global__ void __launch_bounds__(1024) prep_w(const float* __restrict__ W) {
    __shared__ float sm[32][65];
    const int i  = blockIdx.x;
    const int ob = blockIdx.y * 32;
    const int tx = threadIdx.x, ty = threadIdx.y;
#pragma unroll
    for (int k = 0; k < 2; ++k) {
        int d = ty + k * 32;
        sm[tx][d] = W[(size_t)d * IDIM * ODIM + (size_t)i * ODIM + ob + tx];
    }
    __syncthreads();
    __half2 h = __floats2half2_rn(sm[ty][2 * tx], sm[ty][2 * tx + 1]);
    reinterpret_cast<__half2*>(g_Wt)[((size_t)i * ODIM + ob + ty) * 32 + tx] = h;
}

// b1[d][o] fp32 -> g_bt[o][d] fp16
__global__ void __launch_bounds__(1024) prep_b(const float* __restrict__ b1) {
    __shared__ float sm[32][65];
    const int ob = blockIdx.x * 32;
    const int tx = threadIdx.x, ty = threadIdx.y;
#pragma unroll
    for (int k = 0; k < 2; ++k) {
        int d = ty + k * 32;
        sm[tx][d] = b1[(size_t)d * ODIM + ob + tx];
    }
    __syncthreads();
    __half2 h = __floats2half2_rn(sm[ty][2 * tx], sm[ty][2 * tx + 1]);
    reinterpret_cast<__half2*>(g_bt)[(size_t)(ob + ty) * 32 + tx] = h;
}

// ---------------- main kernel ----------------
__global__ void __launch_bounds__(NTH, 2) mlp_mma(
    const float* __restrict__ var,
    float* __restrict__ out)
{
    extern __shared__ __align__(128) uint8_t smem[];
    const uint32_t s0 = smem_u32(smem);
    const uint32_t vS = s0 + V_OFF;

    const int tid  = threadIdx.x;
    const int lane = tid & 31;
    const int w    = tid >> 5;
    const int rowBase = blockIdx.y * BM;
    const int colBase = blockIdx.x * BN;

    const int wm = (w & 3) * 32;    // warp m-base (4 warps over M)
    const int wn = (w >> 2) * 32;   // warp n-base (2 warps over N)
    const int c  = lane & 3;
    const int g  = lane >> 2;

    // ----- stage var as fp16x2 pairs: vh[m][pair d/2], pitch 144B -----
    for (int idx = tid; idx < BM * 32; idx += NTH) {
        int m = idx >> 5, pr = idx & 31;
        float2 vv = *reinterpret_cast<const float2*>(&var[(size_t)(rowBase + m) * DDIM + 2 * pr]);
        __half2 h = __floats2half2_rn(vv.x, vv.y);
        asm volatile("st.shared.b32 [%0], %1;" ::
            "r"(vS + (uint32_t)m * VPITCHB + (uint32_t)pr * 4u),
            "r"(*reinterpret_cast<uint32_t*>(&h)) : "memory");
    }

    // ----- this thread's 4 fragment rows -----
    int xr[4];
    uint32_t vAddr[4];
#pragma unroll
    for (int rr = 0; rr < 4; ++rr) {
        int mloc = wm + (rr >> 1) * 16 + (rr & 1) * 8 + g;
        xr[rr] = rowBase + mloc;
        vAddr[rr] = vS + (uint32_t)mloc * VPITCHB + (uint32_t)c * 4u;
    }

    // ----- B loader (cp.async): o-row = tid/4, two 16B chunks per 128B half -----
    const int bo = tid >> 2;
    const int ci = tid & 3;
    auto issueB = [&](int t) {
        const uint32_t dstBase = s0 + (uint32_t)(t & 3) * B_STAGE + (uint32_t)bo * BPITCHB;
        if (t < NT_W) {
            const __half* p0 = g_Wt + ((size_t)(2 * t) * ODIM + colBase + bo) * DDIM;
            const __half* p1 = p0 + (size_t)ODIM * DDIM;
#pragma unroll
            for (int cc = 0; cc < 2; ++cc) {
                uint32_t ch = (uint32_t)(ci + cc * 4);
                CP_ASYNC16(dstBase + ch * 16u,        p0 + ch * 8);
                CP_ASYNC16(dstBase + 128u + ch * 16u, p1 + ch * 8);
            }
        } else {   // bias half-tile: fill k 0..63 only; k 64..127 annihilated by x=0
            const __half* p0 = g_bt + (size_t)(colBase + bo) * DDIM;
#pragma unroll
            for (int cc = 0; cc < 2; ++cc) {
                uint32_t ch = (uint32_t)(ci + cc * 4);
                CP_ASYNC16(dstBase + ch * 16u, p0 + ch * 8);
            }
        }
        CP_COMMIT();
    };
    auto loadX = [&](int t, float* a0, float* a1) {
        if (t < NT_W) {
#pragma unroll
            for (int rr = 0; rr < 4; ++rr) {
                a0[rr] = __ldg(&g_xT[(size_t)(2 * t) * NROWS + xr[rr]]);
                a1[rr] = __ldg(&g_xT[(size_t)(2 * t + 1) * NROWS + xr[rr]]);
            }
        } else {
#pragma unroll
            for (int rr = 0; rr < 4; ++rr) { a0[rr] = 1.0f; a1[rr] = 0.0f; }
        }
    };

    float C[2][4][4];
#pragma unroll
    for (int mt = 0; mt < 2; ++mt)
#pragma unroll
        for (int nt = 0; nt < 4; ++nt)
#pragma unroll
            for (int q = 0; q < 4; ++q) C[mt][nt][q] = 0.0f;

    // ----- prologue -----
    issueB(0); issueB(1); issueB(2);
    float xc0[4], xc1[4], xn0[4], xn1[4];
    loadX(0, xc0, xc1);
    __syncthreads();   // vh ready

    const uint32_t bRowW = (uint32_t)(wn + g) * BPITCHB + (uint32_t)c * 4u;

    // ----- mainloop -----
    for (int i = 0; i < NTILES; ++i) {
        CP_WAIT2();
        __syncthreads();

        if (i + 3 <= NT_W) issueB(i + 3);
        else CP_COMMIT();             // keep group count flowing so WAIT2 really lands tile i
        loadX(i + 1, xn0, xn1);

        uint32_t xh[2][4];
#pragma unroll
        for (int rr = 0; rr < 4; ++rr) {
            xh[0][rr] = f2h2(xc0[rr]);
            xh[1][rr] = f2h2(xc1[rr]);
        }

        const uint32_t bB0 = s0 + (uint32_t)(i & 3) * B_STAGE + bRowW;

#pragma unroll
        for (int ks = 0; ks < 8; ++ks) {
            const int il = ks >> 2;
            const uint32_t kq32 = (uint32_t)(ks & 3) * 32u;
            // B fragments: k = 16ks + 2c (+1 packed), and +8
            const uint32_t rA = bB0 + (uint32_t)ks * 32u;
            uint32_t b[4][2];
#pragma unroll
            for (int nt = 0; nt < 4; ++nt) {
                LDS32(b[nt][0], rA + (uint32_t)nt * (8u * BPITCHB));
                LDS32(b[nt][1], rA + (uint32_t)nt * (8u * BPITCHB) + 16u);
            }
            // A fragments: one fp16x2 mul per reg
            uint32_t a[2][4];
#pragma unroll
            for (int mt = 0; mt < 2; ++mt) {
                uint32_t v0, v1, v2, v3;
                LDS32(v0, vAddr[mt * 2 + 0] + kq32);
                LDS32(v1, vAddr[mt * 2 + 1] + kq32);
                LDS32(v2, vAddr[mt * 2 + 0] + kq32 + 16u);
                LDS32(v3, vAddr[mt * 2 + 1] + kq32 + 16u);
                HMUL2(a[mt][0], xh[il][mt * 2 + 0], v0);
                HMUL2(a[mt][1], xh[il][mt * 2 + 1], v1);
                HMUL2(a[mt][2], xh[il][mt * 2 + 0], v2);
                HMUL2(a[mt][3], xh[il][mt * 2 + 1], v3);
            }
#pragma unroll
            for (int mt = 0; mt < 2; ++mt)
#pragma unroll
                for (int nt = 0; nt < 4; ++nt)
                    mma_f16_16816(C[mt][nt][0], C[mt][nt][1], C[mt][nt][2], C[mt][nt][3],
                                  a[mt][0], a[mt][1], a[mt][2], a[mt][3],
                                  b[nt][0], b[nt][1]);
        }

#pragma unroll
        for (int rr = 0; rr < 4; ++rr) { xc0[rr] = xn0[rr]; xc1[rr] = xn1[rr]; }
    }

    // ----- epilogue (fp16 RN is unbiased: no compensation scale) -----
#pragma unroll
    for (int mt = 0; mt < 2; ++mt) {
        const int r0 = rowBase + wm + mt * 16 + g;
#pragma unroll
        for (int nt = 0; nt < 4; ++nt) {
            const int c0i = colBase + wn + nt * 8 + c * 2;
            float2 v0, v1;
            v0.x = C[mt][nt][0]; v0.y = C[mt][nt][1];
            v1.x = C[mt][nt][2]; v1.y = C[mt][nt][3];
            *reinterpret_cast<float2*>(&out[(size_t)r0 * ODIM + c0i]) = v0;
            *reinterpret_cast<float2*>(&out[(size_t)(r0 + 8) * ODIM + c0i]) = v1;
        }
    }
}

// ---------------- host ----------------
extern "C" void kernel_launch(void* const* d_in, const int* in_sizes, int n_in,
                              void* d_out, int out_size) {
    const float* x   = (const float*)d_in[0];   // [4096, 512]
    const float* var = (const float*)d_in[1];   // [4096, 64]
    const float* W   = (const float*)d_in[2];   // [64, 512, 512]
    const float* b1  = (const float*)d_in[3];   // [64, 512]
    float* out       = (float*)d_out;           // [4096, 512]

    {
        dim3 tb(32, 32), tg(IDIM / 32, NROWS / 32);
        transpose_x<<<tg, tb>>>(x);
    }
    {
        dim3 tb(32, 32), tg(IDIM, ODIM / 32);
        prep_w<<<tg, tb>>>(W);
    }
    {
        dim3 tb(32, 32);
        prep_b<<<ODIM / 32, tb>>>(b1);
    }

    cudaFuncSetAttribute(mlp_mma, cudaFuncAttributeMaxDynamicSharedMemorySize, SMEM_TOTAL);
    dim3 grid(ODIM / BN, NROWS / BM);   // (8, 32) = 256 CTAs, 2 per SM
    mlp_mma<<<grid, NTH, SMEM_TOTAL>>>(var, out);
}

// round 9
// speedup vs baseline: 2.5454x; 1.0560x over previous
#include <cuda_runtime.h>
#include <cuda_fp16.h>
#include <cstdint>
#include <cstddef>

#define NROWS 4096
#define ODIM  512
#define IDIM  512
#define DDIM  64

#define BM 128
#define BN 64
#define NTH 256
#define NT_W 256            // W tiles, each covering 2 consecutive i (BK = 128)
#define NTILES 257          // + bias half-tile

#define BPITCHB 288u                       // bytes per o-row (72 words ≡ 8 mod 32 -> LDS.64 conflict-free)
#define B_STAGE (64u * BPITCHB)            // 18432 B
#define V_OFF   (4u * B_STAGE)             // 73728
#define VPITCHB 160u                       // bytes per m-row of vh (40 words ≡ 8 mod 32)
#define SMEM_TOTAL (int)(V_OFF + 128u * VPITCHB)   // 94208 B -> 2 CTAs/SM

__device__ float  g_xT[IDIM * NROWS];                  // x transposed: [512][4096] fp32
__device__ __half g_Wt[(size_t)IDIM * ODIM * DDIM];    // W re-laid: [i][o][d-permuted] fp16
__device__ __half g_bt[ODIM * DDIM];                   // b1 re-laid: [o][d-permuted] fp16

// pair-permutation within groups of 8 pairs (16 k): logical j -> phys (j<4 ? 2j : 2(j-4)+1)
__device__ __forceinline__ int pperm(int pr) {
    int gq = pr >> 3, j = pr & 7;
    int pj = (j < 4) ? (2 * j) : (2 * (j - 4) + 1);
    return gq * 8 + pj;
}

// ---------------- helpers ----------------
__device__ __forceinline__ uint32_t smem_u32(const void* p) {
    uint32_t a;
    asm("{ .reg .u64 t; cvta.to.shared.u64 t, %1; cvt.u32.u64 %0, t; }" : "=r"(a) : "l"(p));
    return a;
}
__device__ __forceinline__ uint32_t f2h2(float f) {   // (h,h) packed fp16x2
    uint32_t r;
    asm("{ .reg .b16 h; cvt.rn.f16.f32 h, %1; mov.b32 %0, {h, h}; }" : "=r"(r) : "f"(f));
    return r;
}
#define CP_ASYNC16(dst, src) \
    asm volatile("cp.async.cg.shared.global [%0], [%1], 16;" :: "r"(dst), "l"(src) : "memory")
#define CP_COMMIT() asm volatile("cp.async.commit_group;" ::: "memory")
#define CP_WAIT2()  asm volatile("cp.async.wait_group 2;" ::: "memory")

#define LDS64(lo, hi, a) \
    asm volatile("ld.shared.v2.b32 {%0, %1}, [%2];" : "=r"(lo), "=r"(hi) : "r"(a))
#define HMUL2(d, a, b) asm("mul.rn.f16x2 %0, %1, %2;" : "=r"(d) : "r"(a), "r"(b))

__device__ __forceinline__ void mma_f16_16816(float& c0, float& c1, float& c2, float& c3,
                                              uint32_t a0, uint32_t a1, uint32_t a2, uint32_t a3,
                                              uint32_t b0, uint32_t b1) {
    asm volatile(
        "mma.sync.aligned.m16n8k16.row.col.f32.f16.f16.f32 "
        "{%0,%1,%2,%3}, {%4,%5,%6,%7}, {%8,%9}, {%0,%1,%2,%3};"
        : "+f"(c0), "+f"(c1), "+f"(c2), "+f"(c3)
        : "r"(a0), "r"(a1), "r"(a2), "r"(a3), "r"(b0), "r"(b1));
}

// ---------------- prepass kernels ----------------
__global__ void __launch_bounds__(1024) transpose_x(const float* __restrict__ x) {
    __shared__ float t[32][33];
    const int bi = blockIdx.x * 32;
    const int bn = blockIdx.y * 32;
    t[threadIdx.y][threadIdx.x] = x[(size_t)(bn + threadIdx.y) * IDIM + bi + threadIdx.x];
    __syncthreads();
    g_xT[(size_t)(bi + threadIdx.y) * NROWS + bn + threadIdx.x] = t[threadIdx.x][threadIdx.y];
}

// W[d][i][o] fp32 -> g_Wt[i][o][perm(d)] fp16
__global__ void __launch_bounds__(1024) prep_w(const float* __restrict__ W) {
    __shared__ float sm[32][65];
    const int i  = blockIdx.x;
    const int ob = blockIdx.y * 32;
    const int tx = threadIdx.x, ty = threadIdx.y;
#pragma unroll
    for (int k = 0; k < 2; ++k) {
        int d = ty + k * 32;
        sm[tx][d] = W[(size_t)d * IDIM * ODIM + (size_t)i * ODIM + ob + tx];
    }
    __syncthreads();
    __half2 h = __floats2half2_rn(sm[ty][2 * tx], sm[ty][2 * tx + 1]);
    reinterpret_cast<__half2*>(g_Wt)[((size_t)i * ODIM + ob + ty) * 32 + pperm(tx)] = h;
}

// b1[d][o] fp32 -> g_bt[o][perm(d)] fp16
__global__ void __launch_bounds__(1024) prep_b(const float* __restrict__ b1) {
    __shared__ float sm[32][65];
    const int ob = blockIdx.x * 32;
    const int tx = threadIdx.x, ty = threadIdx.y;
#pragma unroll
    for (int k = 0; k < 2; ++k) {
        int d = ty + k * 32;
        sm[tx][d] = b1[(size_t)d * ODIM + ob + tx];
    }
    __syncthreads();
    __half2 h = __floats2half2_rn(sm[ty][2 * tx], sm[ty][2 * tx + 1]);
    reinterpret_cast<__half2*>(g_bt)[(size_t)(ob + ty) * 32 + pperm(tx)] = h;
}

// ---------------- main kernel ----------------
__global__ void __launch_bounds__(NTH, 2) mlp_mma(
    const float* __restrict__ var,
    float* __restrict__ out)
{
    extern __shared__ __align__(128) uint8_t smem[];
    const uint32_t s0 = smem_u32(smem);
    const uint32_t vS = s0 + V_OFF;

    const int tid  = threadIdx.x;
    const int lane = tid & 31;
    const int w    = tid >> 5;
    const int rowBase = blockIdx.y * BM;
    const int colBase = blockIdx.x * BN;

    const int wm = (w & 3) * 32;    // warp m-base (4 warps over M)
    const int wn = (w >> 2) * 32;   // warp n-base (2 warps over N)
    const int c  = lane & 3;
    const int g  = lane >> 2;

    // ----- stage var as fp16x2 pairs (permuted): vh[m][pperm(d/2)], pitch 160B -----
    for (int idx = tid; idx < BM * 32; idx += NTH) {
        int m = idx >> 5, pr = idx & 31;
        float2 vv = *reinterpret_cast<const float2*>(&var[(size_t)(rowBase + m) * DDIM + 2 * pr]);
        __half2 h = __floats2half2_rn(vv.x, vv.y);
        asm volatile("st.shared.b32 [%0], %1;" ::
            "r"(vS + (uint32_t)m * VPITCHB + (uint32_t)pperm(pr) * 4u),
            "r"(*reinterpret_cast<uint32_t*>(&h)) : "memory");
    }

    // ----- this thread's 4 fragment rows -----
    int xr[4];
    uint32_t vAddr[4];
#pragma unroll
    for (int rr = 0; rr < 4; ++rr) {
        int mloc = wm + (rr >> 1) * 16 + (rr & 1) * 8 + g;
        xr[rr] = rowBase + mloc;
        vAddr[rr] = vS + (uint32_t)mloc * VPITCHB + (uint32_t)c * 8u;  // phys pair 2c
    }

    // ----- B loader (cp.async): o-row = tid/4, two 16B chunks per 128B half -----
    const int bo = tid >> 2;
    const int ci = tid & 3;
    auto issueB = [&](int t) {
        const uint32_t dstBase = s0 + (uint32_t)(t & 3) * B_STAGE + (uint32_t)bo * BPITCHB;
        if (t < NT_W) {
            const __half* p0 = g_Wt + ((size_t)(2 * t) * ODIM + colBase + bo) * DDIM;
            const __half* p1 = p0 + (size_t)ODIM * DDIM;
#pragma unroll
            for (int cc = 0; cc < 2; ++cc) {
                uint32_t ch = (uint32_t)(ci + cc * 4);
                CP_ASYNC16(dstBase + ch * 16u,        p0 + ch * 8);
                CP_ASYNC16(dstBase + 128u + ch * 16u, p1 + ch * 8);
            }
        } else {   // bias half-tile: fill k 0..63 only; k 64..127 annihilated by x=0
            const __half* p0 = g_bt + (size_t)(colBase + bo) * DDIM;
#pragma unroll
            for (int cc = 0; cc < 2; ++cc) {
                uint32_t ch = (uint32_t)(ci + cc * 4);
                CP_ASYNC16(dstBase + ch * 16u, p0 + ch * 8);
            }
        }
        CP_COMMIT();
    };
    auto loadX = [&](int t, float* a0, float* a1) {
        if (t < NT_W) {
#pragma unroll
            for (int rr = 0; rr < 4; ++rr) {
                a0[rr] = __ldg(&g_xT[(size_t)(2 * t) * NROWS + xr[rr]]);
                a1[rr] = __ldg(&g_xT[(size_t)(2 * t + 1) * NROWS + xr[rr]]);
            }
        } else {
#pragma unroll
            for (int rr = 0; rr < 4; ++rr) { a0[rr] = 1.0f; a1[rr] = 0.0f; }
        }
    };

    float C[2][4][4];
#pragma unroll
    for (int mt = 0; mt < 2; ++mt)
#pragma unroll
        for (int nt = 0; nt < 4; ++nt)
#pragma unroll
            for (int q = 0; q < 4; ++q) C[mt][nt][q] = 0.0f;

    // ----- prologue -----
    issueB(0); issueB(1); issueB(2);
    float xc0[4], xc1[4], xn0[4], xn1[4];
    loadX(0, xc0, xc1);
    __syncthreads();   // vh ready

    const uint32_t bRowW = (uint32_t)(wn + g) * BPITCHB + (uint32_t)c * 8u;

    // ----- mainloop -----
    for (int i = 0; i < NTILES; ++i) {
        CP_WAIT2();
        __syncthreads();

        if (i + 3 <= NT_W) issueB(i + 3);
        else CP_COMMIT();             // keep group count flowing so WAIT2 really lands tile i
        loadX(i + 1, xn0, xn1);

        uint32_t xh[2][4];
#pragma unroll
        for (int rr = 0; rr < 4; ++rr) {
            xh[0][rr] = f2h2(xc0[rr]);
            xh[1][rr] = f2h2(xc1[rr]);
        }

        const uint32_t bB0 = s0 + (uint32_t)(i & 3) * B_STAGE + bRowW;

#pragma unroll
        for (int ks = 0; ks < 8; ++ks) {
            const int il = ks >> 2;
            const uint32_t kq32 = (uint32_t)(ks & 3) * 32u;
            // B fragments: one LDS.64 per nt gives {b0 = k2c pair, b1 = k(8+2c) pair}
            const uint32_t rA = bB0 + (uint32_t)ks * 32u;
            uint32_t b[4][2];
#pragma unroll
            for (int nt = 0; nt < 4; ++nt)
                LDS64(b[nt][0], b[nt][1], rA + (uint32_t)nt * (8u * BPITCHB));
            // A fragments: one LDS.64 per row gives {v(pair c), v(pair c+4)}
            uint32_t a[2][4];
#pragma unroll
            for (int mt = 0; mt < 2; ++mt) {
                uint32_t v0, v2, v1, v3;
                LDS64(v0, v2, vAddr[mt * 2 + 0] + kq32);
                LDS64(v1, v3, vAddr[mt * 2 + 1] + kq32);
                HMUL2(a[mt][0], xh[il][mt * 2 + 0], v0);
                HMUL2(a[mt][1], xh[il][mt * 2 + 1], v1);
                HMUL2(a[mt][2], xh[il][mt * 2 + 0], v2);
                HMUL2(a[mt][3], xh[il][mt * 2 + 1], v3);
            }
#pragma unroll
            for (int mt = 0; mt < 2; ++mt)
#pragma unroll
                for (int nt = 0; nt < 4; ++nt)
                    mma_f16_16816(C[mt][nt][0], C[mt][nt][1], C[mt][nt][2], C[mt][nt][3],
                                  a[mt][0], a[mt][1], a[mt][2], a[mt][3],
                                  b[nt][0], b[nt][1]);
        }

#pragma unroll
        for (int rr = 0; rr < 4; ++rr) { xc0[rr] = xn0[rr]; xc1[rr] = xn1[rr]; }
    }

    // ----- epilogue -----
#pragma unroll
    for (int mt = 0; mt < 2; ++mt) {
        const int r0 = rowBase + wm + mt * 16 + g;
#pragma unroll
        for (int nt = 0; nt < 4; ++nt) {
            const int c0i = colBase + wn + nt * 8 + c * 2;
            float2 v0, v1;
            v0.x = C[mt][nt][0]; v0.y = C[mt][nt][1];
            v1.x = C[mt][nt][2]; v1.y = C[mt][nt][3];
            *reinterpret_cast<float2*>(&out[(size_t)r0 * ODIM + c0i]) = v0;
            *reinterpret_cast<float2*>(&out[(size_t)(r0 + 8) * ODIM + c0i]) = v1;
        }
    }
}

// ---------------- host ----------------
extern "C" void kernel_launch(void* const* d_in, const int* in_sizes, int n_in,
                              void* d_out, int out_size) {
    const float* x   = (const float*)d_in[0];   // [4096, 512]
    const float* var = (const float*)d_in[1];   // [4096, 64]
    const float* W   = (const float*)d_in[2];   // [64, 512, 512]
    const float* b1  = (const float*)d_in[3];   // [64, 512]
    float* out       = (float*)d_out;           // [4096, 512]

    {
        dim3 tb(32, 32), tg(IDIM / 32, NROWS / 32);
        transpose_x<<<tg, tb>>>(x);
    }
    {
        dim3 tb(32, 32), tg(IDIM, ODIM / 32);
        prep_w<<<tg, tb>>>(W);
    }
    {
        dim3 tb(32, 32);
        prep_b<<<ODIM / 32, tb>>>(b1);
    }

    cudaFuncSetAttribute(mlp_mma, cudaFuncAttributeMaxDynamicSharedMemorySize, SMEM_TOTAL);
    dim3 grid(ODIM / BN, NROWS / BM);   // (8, 32) = 256 CTAs, 2 per SM
    mlp_mma<<<grid, NTH, SMEM_TOTAL>>>(var, out);
}